// round 9
// baseline (speedup 1.0000x reference)
#include <cuda_runtime.h>
#include <cuda_bf16.h>
#include <math.h>
#include <stdint.h>

// Problem constants
constexpr int BB = 512;      // batch (M)
constexpr int EE = 512;      // embedding dim (K)
constexpr int CC = 100000;   // classes (N)
constexpr int NT = (CC + 127) / 128;   // 782 N-tiles
constexpr int NTILES = 4 * NT;         // 3128 total tiles
constexpr int CTAS = 296;              // 2 per SM; 296 % 4 == 0 -> fixed M-tile per CTA

// ArcFace constants (margin = 0.5)
#define COS_M   0.8775825618903728f
#define SIN_M   0.479425538604203f
#define MM_C    0.23971276930210156f
#define THRESH  (-0.8775825618903728f)
#define S_SCALE 64.0f

// ---------------------------------------------------------------------------
// Static device scratch (allocations are forbidden)
// ---------------------------------------------------------------------------
__device__ float         g_row_loss[BB];
__device__ float         g_partial[(size_t)BB * NT];
__device__ __nv_bfloat16 g_kT_hi[(size_t)CC * EE];   // knormT [C][K] hi
__device__ __nv_bfloat16 g_kT_lo[(size_t)CC * EE];   // knormT [C][K] lo
__device__ __nv_bfloat16 g_emb_hi[(size_t)BB * EE];  // emb [B][K] hi
__device__ __nv_bfloat16 g_emb_lo[(size_t)BB * EE];  // emb [B][K] lo

// ---------------------------------------------------------------------------
// PTX helpers: baseline (non-'a') instructions only
// ---------------------------------------------------------------------------
__device__ __forceinline__ uint32_t smem_u32(const void* p) {
    uint32_t a;
    asm("{ .reg .u64 t; cvta.to.shared.u64 t, %1; cvt.u32.u64 %0, t; }"
        : "=r"(a) : "l"(p));
    return a;
}

__device__ __forceinline__ void ldsm_x4(uint32_t* r, uint32_t a) {
    asm volatile("ldmatrix.sync.aligned.m8n8.x4.shared.b16 {%0,%1,%2,%3}, [%4];"
        : "=r"(r[0]), "=r"(r[1]), "=r"(r[2]), "=r"(r[3]) : "r"(a));
}
__device__ __forceinline__ void mma_bf16(float* d, const uint32_t* a, const uint32_t* b) {
    asm volatile(
        "mma.sync.aligned.m16n8k16.row.col.f32.bf16.bf16.f32 "
        "{%0,%1,%2,%3}, {%4,%5,%6,%7}, {%8,%9}, {%0,%1,%2,%3};"
        : "+f"(d[0]), "+f"(d[1]), "+f"(d[2]), "+f"(d[3])
        : "r"(a[0]), "r"(a[1]), "r"(a[2]), "r"(a[3]), "r"(b[0]), "r"(b[1]));
}
__device__ __forceinline__ void cp16(uint32_t dst, const void* src, int sz) {
    asm volatile("cp.async.cg.shared.global [%0], [%1], 16, %2;"
        :: "r"(dst), "l"(src), "r"(sz) : "memory");
}
#define CP_COMMIT() asm volatile("cp.async.commit_group;" ::: "memory")
#define CP_WAIT0()  asm volatile("cp.async.wait_group 0;" ::: "memory")

// ---------------------------------------------------------------------------
// Kernel 1 (fused): single pass over ker -> norms + normalized transpose split.
// ---------------------------------------------------------------------------
__global__ __launch_bounds__(256) void prep_ker_fused(const float* __restrict__ ker) {
    __shared__ float sm[32][513];
    __shared__ float s_inv[32];

    const int tid  = threadIdx.x;
    const int lane = tid & 31;
    const int wid  = tid >> 5;
    const int c0   = blockIdx.x * 32;

    #pragma unroll
    for (int i = 0; i < 64; i++) {
        int k = wid + i * 8;
        sm[lane][k] = ker[(size_t)k * CC + (c0 + lane)];
    }
    __syncthreads();

    #pragma unroll
    for (int i = 0; i < 4; i++) {
        int c = wid + i * 8;
        float s = 0.f;
        #pragma unroll
        for (int j = 0; j < 16; j++) {
            float v = sm[c][lane + j * 32];
            s = fmaf(v, v, s);
        }
        #pragma unroll
        for (int off = 16; off > 0; off >>= 1)
            s += __shfl_xor_sync(0xffffffff, s, off);
        if (lane == 0) s_inv[c] = 1.0f / (sqrtf(s) + 1e-6f);
    }
    __syncthreads();

    #pragma unroll
    for (int i = 0; i < 4; i++) {
        int c = wid + i * 8;
        const float inv = s_inv[c];
        size_t base = (size_t)(c0 + c) * EE;
        #pragma unroll
        for (int j = 0; j < 16; j++) {
            int k = lane + j * 32;
            float v = sm[c][k] * inv;
            __nv_bfloat16 h = __float2bfloat16(v);
            g_kT_hi[base + k] = h;
            g_kT_lo[base + k] = __float2bfloat16(v - __bfloat162float(h));
        }
    }
}

// ---------------------------------------------------------------------------
// Kernel 2: split emb to bf16 hi/lo
// ---------------------------------------------------------------------------
__global__ void prep_emb_kernel(const float* __restrict__ emb) {
    int i = blockIdx.x * blockDim.x + threadIdx.x;
    if (i >= BB * EE) return;
    float v = emb[i];
    __nv_bfloat16 h = __float2bfloat16(v);
    g_emb_hi[i] = h;
    g_emb_lo[i] = __float2bfloat16(v - __bfloat162float(h));
}

// ---------------------------------------------------------------------------
// Kernel 3: PERSISTENT mma.sync bf16 split-3 GEMM + fused arcface epilogue.
// 296 CTAs x 256 threads, 2 CTAs/SM, fixed M-tile per CTA, tiles strided 296.
// Next tile's stage-0 load is issued before the epilogue and overlaps it.
// ---------------------------------------------------------------------------
constexpr int ROWB   = 80;                    // padded row bytes (conflict-free)
constexpr int MATB   = 128 * ROWB;            // 10240 B per matrix
constexpr int STAGEB = 4 * MATB;              // 40960 B per stage
constexpr int DYNB   = 2 * STAGEB;            // 81920 B dynamic smem

__global__ __launch_bounds__(256, 2) void gemm_mma_kernel(
    const int* __restrict__ label,
    float* __restrict__ out_logits, float* __restrict__ out_cos)
{
    extern __shared__ char dyn[];
    __shared__ float srows[128 * 4];          // epilogue scratch (NOT stage bufs)

    const int tid  = threadIdx.x;
    const int lane = tid & 31;
    const int wid  = tid >> 5;
    const int wm   = wid >> 2;     // 0..1
    const int wn   = wid & 3;      // 0..3
    const uint32_t sbase = smem_u32(dyn);

    // fixed M-tile for this CTA (blockIdx.x % 4 stays constant under +=296)
    const int mx = blockIdx.x & 3;
    const int r0 = mx * 128;

    // ---- G->S load mapping: 64 threads per matrix, 8 cp.async each ----
    const int mat  = tid >> 6;       // 0:Ahi 1:Alo 2:Bhi 3:Blo
    const int t6   = tid & 63;
    const int ch   = t6 & 3;
    const int rrow = t6 >> 2;
    const __nv_bfloat16* gpA;        // A: fixed rows
    const __nv_bfloat16* gpB;        // B: add c0*EE per tile
    if (mat == 0)      { gpA = g_emb_hi + (size_t)(r0 + rrow) * EE; gpB = nullptr; }
    else if (mat == 1) { gpA = g_emb_lo + (size_t)(r0 + rrow) * EE; gpB = nullptr; }
    else if (mat == 2) { gpA = nullptr; gpB = g_kT_hi + (size_t)rrow * EE; }
    else               { gpA = nullptr; gpB = g_kT_lo + (size_t)rrow * EE; }
    const bool isB = (mat >= 2);

    auto load_stage = [&](int s, int c0, int kc) {
        uint32_t dst0 = sbase + s * STAGEB + mat * MATB + rrow * ROWB + ch * 16;
        const __nv_bfloat16* p = isB
            ? gpB + (size_t)c0 * EE + kc * 32 + ch * 8
            : gpA + kc * 32 + ch * 8;
        #pragma unroll
        for (int j = 0; j < 8; j++) {
            int sz = 16;
            if (isB && (c0 + rrow + j * 16) >= CC) sz = 0;
            cp16(dst0 + j * 16 * ROWB, p + (size_t)j * 16 * EE, sz);
        }
    };

    // Term-major issue order: same-acc MMAs are 8 issues apart.
    float acc[4][4][4];
    auto compute_stage = [&](int s) {
        const uint32_t st = sbase + s * STAGEB;
        #pragma unroll
        for (int kk = 0; kk < 2; kk++) {
            uint32_t ah[4][4], al[4][4];
            #pragma unroll
            for (int mt = 0; mt < 4; mt++) {
                uint32_t ad = st + (uint32_t)((wm * 64 + mt * 16 + (lane & 15)) * ROWB
                                              + (lane >> 4) * 16 + kk * 32);
                ldsm_x4(ah[mt], ad);
                ldsm_x4(al[mt], ad + MATB);
            }
            #pragma unroll
            for (int np = 0; np < 2; np++) {
                uint32_t bh[4], bl[4];
                uint32_t bd = st + 2 * MATB
                            + (uint32_t)((wn * 32 + (np * 2 + ((lane >> 4) & 1)) * 8
                                          + (lane & 7)) * ROWB
                                         + ((lane >> 3) & 1) * 16 + kk * 32);
                ldsm_x4(bh, bd);
                ldsm_x4(bl, bd + MATB);
                const int n0 = np * 2, n1 = np * 2 + 1;
                #pragma unroll
                for (int mt = 0; mt < 4; mt++) mma_bf16(acc[mt][n0], ah[mt], bh + 0);
                #pragma unroll
                for (int mt = 0; mt < 4; mt++) mma_bf16(acc[mt][n1], ah[mt], bh + 2);
                #pragma unroll
                for (int mt = 0; mt < 4; mt++) mma_bf16(acc[mt][n0], ah[mt], bl + 0);
                #pragma unroll
                for (int mt = 0; mt < 4; mt++) mma_bf16(acc[mt][n1], ah[mt], bl + 2);
                #pragma unroll
                for (int mt = 0; mt < 4; mt++) mma_bf16(acc[mt][n0], al[mt], bh + 0);
                #pragma unroll
                for (int mt = 0; mt < 4; mt++) mma_bf16(acc[mt][n1], al[mt], bh + 2);
            }
        }
    };

    // labels for this CTA's fixed rows (hoisted out of the tile loop)
    const int lq = lane >> 2;
    const int lc = 2 * (lane & 3);
    int lbs[4][2];
    #pragma unroll
    for (int mt = 0; mt < 4; mt++) {
        lbs[mt][0] = label[r0 + wm * 64 + mt * 16 + lq];
        lbs[mt][1] = label[r0 + wm * 64 + mt * 16 + lq + 8];
    }

    // prologue: stage 0 of the first tile
    {
        const int g0 = blockIdx.x;
        load_stage(0, (g0 >> 2) * 128, 0);
        CP_COMMIT();
    }

    // ---- persistent tile loop ----
    for (int g = blockIdx.x; g < NTILES; g += CTAS) {
        const int ny = g >> 2;
        const int c0 = ny * 128;

        CP_WAIT0();          // stage 0 (loaded during prev epilogue) complete
        __syncthreads();

        #pragma unroll
        for (int mt = 0; mt < 4; mt++)
            #pragma unroll
            for (int nt = 0; nt < 4; nt++)
                #pragma unroll
                for (int v = 0; v < 4; v++) acc[mt][nt][v] = 0.f;

        for (int kc = 0; kc < 16; kc++) {
            if (kc < 15) {
                load_stage((kc + 1) & 1, c0, kc + 1);
                CP_COMMIT();
            } else {
                const int gn = g + CTAS;
                if (gn < NTILES) {           // next tile stage 0 -> buffer 0
                    load_stage(0, (gn >> 2) * 128, 0);
                    CP_COMMIT();
                }
            }
            compute_stage(kc & 1);
            if (kc < 15) {
                CP_WAIT0();
                __syncthreads();
            }
            // kc==15: next-tile load left in flight; it overlaps the epilogue
        }

        // ---- epilogue (stage buffers untouched; overlaps in-flight load) ----
        float rsum[4][2];
        #pragma unroll
        for (int mt = 0; mt < 4; mt++) { rsum[mt][0] = 0.f; rsum[mt][1] = 0.f; }

        const bool full_tile = (c0 + 128 <= CC);

        #pragma unroll
        for (int mt = 0; mt < 4; mt++) {
            #pragma unroll
            for (int nt = 0; nt < 4; nt++) {
                #pragma unroll
                for (int v = 0; v < 4; v++) {
                    const int h    = v >> 1;
                    const int grow = r0 + wm * 64 + mt * 16 + lq + h * 8;
                    const int col  = c0 + wn * 32 + nt * 8 + lc + (v & 1);
                    if (full_tile || col < CC) {
                        float cs = acc[mt][nt][v];
                        cs = fminf(1.0f, fmaxf(-1.0f, cs));
                        float o = cs;
                        if (col == lbs[mt][h]) {
                            float sn = sqrtf(fmaxf(0.f, 1.0f - cs * cs));
                            float cm = fmaf(cs, COS_M, -sn * SIN_M);
                            o = (cs - THRESH <= 0.f) ? (cs - MM_C) : cm;
                        }
                        float lg = o * S_SCALE;
                        size_t ga = (size_t)grow * CC + col;
                        out_logits[ga] = lg;
                        out_cos[ga]    = cs;
                        rsum[mt][h] += __expf(lg - 64.0f);
                    }
                }
            }
        }

        #pragma unroll
        for (int mt = 0; mt < 4; mt++)
            #pragma unroll
            for (int h = 0; h < 2; h++) {
                float s = rsum[mt][h];
                s += __shfl_xor_sync(0xffffffff, s, 1);
                s += __shfl_xor_sync(0xffffffff, s, 2);
                rsum[mt][h] = s;
            }

        __syncthreads();   // srows reuse safety across tile iterations
        if ((lane & 3) == 0) {
            #pragma unroll
            for (int mt = 0; mt < 4; mt++)
                #pragma unroll
                for (int h = 0; h < 2; h++)
                    srows[(wm * 64 + mt * 16 + lq + h * 8) * 4 + wn] = rsum[mt][h];
        }
        __syncthreads();
        if (tid < 128) {
            float s = srows[tid * 4 + 0] + srows[tid * 4 + 1]
                    + srows[tid * 4 + 2] + srows[tid * 4 + 3];
            g_partial[(size_t)(r0 + tid) * NT + ny] = s;
        }
    }
}

// ---------------------------------------------------------------------------
// Kernel 4: per-row reduce of partial sum-exps -> row loss
// ---------------------------------------------------------------------------
__global__ void row_reduce_kernel(const float* __restrict__ out_logits,
                                  const int* __restrict__ label) {
    const int row = blockIdx.x;
    float s = 0.f;
    for (int i = threadIdx.x; i < NT; i += 256)
        s += g_partial[(size_t)row * NT + i];
    __shared__ float sm[256];
    sm[threadIdx.x] = s;
    __syncthreads();
    #pragma unroll
    for (int off = 128; off > 0; off >>= 1) {
        if (threadIdx.x < off) sm[threadIdx.x] += sm[threadIdx.x + off];
        __syncthreads();
    }
    if (threadIdx.x == 0) {
        float logZ = 64.0f + logf(sm[0]);
        g_row_loss[row] = logZ - out_logits[(size_t)row * CC + label[row]];
    }
}

// ---------------------------------------------------------------------------
// Kernel 5: mean over rows -> loss scalar
// ---------------------------------------------------------------------------
__global__ void final_loss_kernel(float* __restrict__ loss_out) {
    __shared__ float sm[BB];
    const int t = threadIdx.x;
    sm[t] = g_row_loss[t];
    __syncthreads();
    #pragma unroll
    for (int off = BB / 2; off > 0; off >>= 1) {
        if (t < off) sm[t] += sm[t + off];
        __syncthreads();
    }
    if (t == 0) loss_out[0] = sm[0] / (float)BB;
}

// ---------------------------------------------------------------------------
extern "C" void kernel_launch(void* const* d_in, const int* in_sizes, int n_in,
                              void* d_out, int out_size) {
    const float* emb   = (const float*)d_in[0];
    const float* ker   = (const float*)d_in[1];
    const int*   label = (const int*)d_in[2];

    float* o          = (float*)d_out;
    float* loss_ptr   = o;
    float* out_logits = o + 1;
    float* out_cos    = o + 1 + (size_t)BB * CC;

    cudaFuncSetAttribute(gemm_mma_kernel,
                         cudaFuncAttributeMaxDynamicSharedMemorySize, DYNB);

    prep_ker_fused<<<CC / 32, 256>>>(ker);
    prep_emb_kernel<<<(BB * EE + 255) / 256, 256>>>(emb);

    gemm_mma_kernel<<<CTAS, 256, DYNB>>>(label, out_logits, out_cos);

    row_reduce_kernel<<<BB, 256>>>(out_logits, label);
    final_loss_kernel<<<1, BB>>>(loss_ptr);
}

// round 10
// speedup vs baseline: 1.2154x; 1.2154x over previous
#include <cuda_runtime.h>
#include <cuda_fp16.h>
#include <math.h>
#include <stdint.h>

// Problem constants
constexpr int BB = 512;      // batch (M)
constexpr int EE = 512;      // embedding dim (K)
constexpr int CC = 100000;   // classes (N)
constexpr int NT = (CC + 127) / 128;   // 782 N-tiles

// ArcFace constants (margin = 0.5)
#define COS_M   0.8775825618903728f
#define SIN_M   0.479425538604203f
#define MM_C    0.23971276930210156f
#define THRESH  (-0.8775825618903728f)
#define S_SCALE 64.0f

// ---------------------------------------------------------------------------
// Static device scratch (allocations are forbidden)
// ---------------------------------------------------------------------------
__device__ float  g_row_loss[BB];
__device__ float  g_partial[(size_t)BB * NT];
__device__ __half g_kT_h16[(size_t)CC * EE];   // knormT [C][K] fp16 hi
__device__ __half g_kT_l16[(size_t)CC * EE];   // knormT [C][K] fp16 lo
__device__ __half g_emb_h16[(size_t)BB * EE];  // emb [B][K] fp16 (hi only)

// ---------------------------------------------------------------------------
// PTX helpers: baseline (non-'a') instructions only
// ---------------------------------------------------------------------------
__device__ __forceinline__ uint32_t smem_u32(const void* p) {
    uint32_t a;
    asm("{ .reg .u64 t; cvta.to.shared.u64 t, %1; cvt.u32.u64 %0, t; }"
        : "=r"(a) : "l"(p));
    return a;
}

__device__ __forceinline__ void ldsm_x4(uint32_t* r, uint32_t a) {
    asm volatile("ldmatrix.sync.aligned.m8n8.x4.shared.b16 {%0,%1,%2,%3}, [%4];"
        : "=r"(r[0]), "=r"(r[1]), "=r"(r[2]), "=r"(r[3]) : "r"(a));
}
__device__ __forceinline__ void mma_f16(float* d, const uint32_t* a, const uint32_t* b) {
    asm volatile(
        "mma.sync.aligned.m16n8k16.row.col.f32.f16.f16.f32 "
        "{%0,%1,%2,%3}, {%4,%5,%6,%7}, {%8,%9}, {%0,%1,%2,%3};"
        : "+f"(d[0]), "+f"(d[1]), "+f"(d[2]), "+f"(d[3])
        : "r"(a[0]), "r"(a[1]), "r"(a[2]), "r"(a[3]), "r"(b[0]), "r"(b[1]));
}
__device__ __forceinline__ void cp16(uint32_t dst, const void* src, int sz) {
    asm volatile("cp.async.cg.shared.global [%0], [%1], 16, %2;"
        :: "r"(dst), "l"(src), "r"(sz) : "memory");
}
#define CP_COMMIT() asm volatile("cp.async.commit_group;" ::: "memory")
#define CP_WAIT0()  asm volatile("cp.async.wait_group 0;" ::: "memory")

// ---------------------------------------------------------------------------
// Kernel 1 (fused): single pass over ker -> norms + normalized transpose,
// fp16 hi/lo split.
// ---------------------------------------------------------------------------
__global__ __launch_bounds__(256) void prep_ker_fused(const float* __restrict__ ker) {
    __shared__ float sm[32][513];
    __shared__ float s_inv[32];

    const int tid  = threadIdx.x;
    const int lane = tid & 31;
    const int wid  = tid >> 5;
    const int c0   = blockIdx.x * 32;

    #pragma unroll
    for (int i = 0; i < 64; i++) {
        int k = wid + i * 8;
        sm[lane][k] = ker[(size_t)k * CC + (c0 + lane)];
    }
    __syncthreads();

    #pragma unroll
    for (int i = 0; i < 4; i++) {
        int c = wid + i * 8;
        float s = 0.f;
        #pragma unroll
        for (int j = 0; j < 16; j++) {
            float v = sm[c][lane + j * 32];
            s = fmaf(v, v, s);
        }
        #pragma unroll
        for (int off = 16; off > 0; off >>= 1)
            s += __shfl_xor_sync(0xffffffff, s, off);
        if (lane == 0) s_inv[c] = 1.0f / (sqrtf(s) + 1e-6f);
    }
    __syncthreads();

    #pragma unroll
    for (int i = 0; i < 4; i++) {
        int c = wid + i * 8;
        const float inv = s_inv[c];
        size_t base = (size_t)(c0 + c) * EE;
        #pragma unroll
        for (int j = 0; j < 16; j++) {
            int k = lane + j * 32;
            float v = sm[c][k] * inv;
            __half h = __float2half(v);
            g_kT_h16[base + k] = h;
            g_kT_l16[base + k] = __float2half(v - __half2float(h));
        }
    }
}

// ---------------------------------------------------------------------------
// Kernel 2: emb -> fp16 (hi only; A-side 2^-12 truncation is the error floor)
// ---------------------------------------------------------------------------
__global__ void prep_emb_kernel(const float* __restrict__ emb) {
    int i = blockIdx.x * blockDim.x + threadIdx.x;
    if (i >= BB * EE) return;
    g_emb_h16[i] = __float2half(emb[i]);
}

// ---------------------------------------------------------------------------
// Kernel 3: mma.sync fp16 2-term GEMM + fused arcface epilogue.
// 256 threads, 2 CTAs/SM, warp grid 2x4, warp tile 64x32.
// D = Ah*Bh + Ah*Bl  (A fp16, B split fp16 hi/lo) -> 2 MMAs per k-step.
// ---------------------------------------------------------------------------
constexpr int ROWB   = 80;                    // 64B data + 16B pad (conflict-free)
constexpr int MATB   = 128 * ROWB;            // 10240 B per matrix
constexpr int STAGEB = 3 * MATB;              // 30720 B per stage (Ah, Bh, Bl)
constexpr int DYNB   = 2 * STAGEB;            // 61440 B dynamic smem

__global__ __launch_bounds__(256, 2) void gemm_mma_kernel(
    const int* __restrict__ label,
    float* __restrict__ out_logits, float* __restrict__ out_cos)
{
    extern __shared__ char dyn[];
    const int tid  = threadIdx.x;
    const int lane = tid & 31;
    const int wid  = tid >> 5;
    const int wm   = wid >> 2;     // 0..1
    const int wn   = wid & 3;      // 0..3
    const int r0 = blockIdx.x * 128;
    const int c0 = blockIdx.y * 128;
    const uint32_t sbase = smem_u32(dyn);

    float acc[4][4][4];
    #pragma unroll
    for (int mt = 0; mt < 4; mt++)
        #pragma unroll
        for (int nt = 0; nt < 4; nt++)
            #pragma unroll
            for (int v = 0; v < 4; v++) acc[mt][nt][v] = 0.f;

    // ---- G->S: 1536 16B-chunks per stage (3 mats x 128 rows x 4), 6/thread ----
    auto load_stage = [&](int s, int kc) {
        const uint32_t stg = sbase + s * STAGEB;
        #pragma unroll
        for (int i = 0; i < 6; i++) {
            int f   = tid + i * 256;
            int m   = f >> 9;          // 0:Ah 1:Bh 2:Bl
            int c   = f & 511;
            int row = c >> 2;
            int ch4 = c & 3;
            uint32_t dst = stg + (uint32_t)(m * MATB + row * ROWB + ch4 * 16);
            const __half* src;
            int sz = 16;
            if (m == 0) {
                src = g_emb_h16 + (size_t)(r0 + row) * EE + kc * 32 + ch4 * 8;
            } else {
                const __half* base = (m == 1) ? g_kT_h16 : g_kT_l16;
                src = base + (size_t)(c0 + row) * EE + kc * 32 + ch4 * 8;
                if (c0 + row >= CC) sz = 0;
            }
            cp16(dst, src, sz);
        }
    };

    // Term-major issue order: same-acc MMAs are 8 issues apart.
    auto compute_stage = [&](int s) {
        const uint32_t st = sbase + s * STAGEB;
        #pragma unroll
        for (int kk = 0; kk < 2; kk++) {
            uint32_t ah[4][4];
            #pragma unroll
            for (int mt = 0; mt < 4; mt++) {
                uint32_t ad = st + (uint32_t)((wm * 64 + mt * 16 + (lane & 15)) * ROWB
                                              + (lane >> 4) * 16 + kk * 32);
                ldsm_x4(ah[mt], ad);
            }
            #pragma unroll
            for (int np = 0; np < 2; np++) {
                uint32_t bh[4], bl[4];
                uint32_t bd = st + MATB
                            + (uint32_t)((wn * 32 + (np * 2 + ((lane >> 4) & 1)) * 8
                                          + (lane & 7)) * ROWB
                                         + ((lane >> 3) & 1) * 16 + kk * 32);
                ldsm_x4(bh, bd);
                ldsm_x4(bl, bd + MATB);
                const int n0 = np * 2, n1 = np * 2 + 1;
                // term 1: Ah*Bh
                #pragma unroll
                for (int mt = 0; mt < 4; mt++) mma_f16(acc[mt][n0], ah[mt], bh + 0);
                #pragma unroll
                for (int mt = 0; mt < 4; mt++) mma_f16(acc[mt][n1], ah[mt], bh + 2);
                // term 2: Ah*Bl
                #pragma unroll
                for (int mt = 0; mt < 4; mt++) mma_f16(acc[mt][n0], ah[mt], bl + 0);
                #pragma unroll
                for (int mt = 0; mt < 4; mt++) mma_f16(acc[mt][n1], ah[mt], bl + 2);
            }
        }
    };

    // ---- pipeline: double-buffered over 16 K-chunks of 32 ----
    load_stage(0, 0);
    CP_COMMIT();
    CP_WAIT0();
    __syncthreads();
    for (int kc = 0; kc < 16; kc++) {
        if (kc < 15) { load_stage((kc + 1) & 1, kc + 1); CP_COMMIT(); }
        compute_stage(kc & 1);
        CP_WAIT0();
        __syncthreads();
    }

    // ---- epilogue: arcface + SCALAR stores + per-row partial sum-exp ----
    const int lq = lane >> 2;
    const int lc = 2 * (lane & 3);
    int lbs[4][2];
    #pragma unroll
    for (int mt = 0; mt < 4; mt++) {
        lbs[mt][0] = label[r0 + wm * 64 + mt * 16 + lq];
        lbs[mt][1] = label[r0 + wm * 64 + mt * 16 + lq + 8];
    }

    float rsum[4][2];
    #pragma unroll
    for (int mt = 0; mt < 4; mt++) { rsum[mt][0] = 0.f; rsum[mt][1] = 0.f; }

    const bool full_tile = (c0 + 128 <= CC);   // true for 781/782 strips

    #pragma unroll
    for (int mt = 0; mt < 4; mt++) {
        #pragma unroll
        for (int nt = 0; nt < 4; nt++) {
            #pragma unroll
            for (int v = 0; v < 4; v++) {
                const int h    = v >> 1;
                const int grow = r0 + wm * 64 + mt * 16 + lq + h * 8;
                const int col  = c0 + wn * 32 + nt * 8 + lc + (v & 1);
                if (full_tile || col < CC) {
                    float cs = acc[mt][nt][v];
                    cs = fminf(1.0f, fmaxf(-1.0f, cs));
                    float o = cs;
                    if (col == lbs[mt][h]) {
                        float sn = sqrtf(fmaxf(0.f, 1.0f - cs * cs));
                        float cm = fmaf(cs, COS_M, -sn * SIN_M);
                        o = (cs - THRESH <= 0.f) ? (cs - MM_C) : cm;
                    }
                    float lg = o * S_SCALE;
                    size_t ga = (size_t)grow * CC + col;
                    out_logits[ga] = lg;
                    out_cos[ga]    = cs;
                    rsum[mt][h] += __expf(lg - 64.0f);
                }
            }
        }
    }

    #pragma unroll
    for (int mt = 0; mt < 4; mt++)
        #pragma unroll
        for (int h = 0; h < 2; h++) {
            float s = rsum[mt][h];
            s += __shfl_xor_sync(0xffffffff, s, 1);
            s += __shfl_xor_sync(0xffffffff, s, 2);
            rsum[mt][h] = s;
        }

    float* srows = (float*)dyn;   // safe: all stage reads complete
    __syncthreads();
    if ((lane & 3) == 0) {
        #pragma unroll
        for (int mt = 0; mt < 4; mt++)
            #pragma unroll
            for (int h = 0; h < 2; h++)
                srows[(wm * 64 + mt * 16 + lq + h * 8) * 4 + wn] = rsum[mt][h];
    }
    __syncthreads();
    if (tid < 128) {
        float s = srows[tid * 4 + 0] + srows[tid * 4 + 1]
                + srows[tid * 4 + 2] + srows[tid * 4 + 3];
        g_partial[(size_t)(r0 + tid) * NT + blockIdx.y] = s;
    }
}

// ---------------------------------------------------------------------------
// Kernel 4: per-row reduce of partial sum-exps -> row loss
// ---------------------------------------------------------------------------
__global__ void row_reduce_kernel(const float* __restrict__ out_logits,
                                  const int* __restrict__ label) {
    const int row = blockIdx.x;
    float s = 0.f;
    for (int i = threadIdx.x; i < NT; i += 256)
        s += g_partial[(size_t)row * NT + i];
    __shared__ float sm[256];
    sm[threadIdx.x] = s;
    __syncthreads();
    #pragma unroll
    for (int off = 128; off > 0; off >>= 1) {
        if (threadIdx.x < off) sm[threadIdx.x] += sm[threadIdx.x + off];
        __syncthreads();
    }
    if (threadIdx.x == 0) {
        float logZ = 64.0f + logf(sm[0]);
        g_row_loss[row] = logZ - out_logits[(size_t)row * CC + label[row]];
    }
}

// ---------------------------------------------------------------------------
// Kernel 5: mean over rows -> loss scalar
// ---------------------------------------------------------------------------
__global__ void final_loss_kernel(float* __restrict__ loss_out) {
    __shared__ float sm[BB];
    const int t = threadIdx.x;
    sm[t] = g_row_loss[t];
    __syncthreads();
    #pragma unroll
    for (int off = BB / 2; off > 0; off >>= 1) {
        if (t < off) sm[t] += sm[t + off];
        __syncthreads();
    }
    if (t == 0) loss_out[0] = sm[0] / (float)BB;
}

// ---------------------------------------------------------------------------
extern "C" void kernel_launch(void* const* d_in, const int* in_sizes, int n_in,
                              void* d_out, int out_size) {
    const float* emb   = (const float*)d_in[0];
    const float* ker   = (const float*)d_in[1];
    const int*   label = (const int*)d_in[2];

    float* o          = (float*)d_out;
    float* loss_ptr   = o;
    float* out_logits = o + 1;
    float* out_cos    = o + 1 + (size_t)BB * CC;

    cudaFuncSetAttribute(gemm_mma_kernel,
                         cudaFuncAttributeMaxDynamicSharedMemorySize, DYNB);

    prep_ker_fused<<<CC / 32, 256>>>(ker);
    prep_emb_kernel<<<(BB * EE + 255) / 256, 256>>>(emb);

    dim3 grid(4, NT);   // x fastest: adjacent bids share the ker N-strip in L2
    gemm_mma_kernel<<<grid, 256, DYNB>>>(label, out_logits, out_cos);

    row_reduce_kernel<<<BB, 256>>>(out_logits, label);
    final_loss_kernel<<<1, BB>>>(loss_ptr);
}

// round 11
// speedup vs baseline: 1.3086x; 1.0767x over previous
#include <cuda_runtime.h>
#include <cuda_fp16.h>
#include <math.h>
#include <stdint.h>

// Problem constants
constexpr int BB = 512;      // batch (M)
constexpr int EE = 512;      // embedding dim (K)
constexpr int CC = 100000;   // classes (N)
constexpr int NT = (CC + 127) / 128;   // 782 N-tiles

// ArcFace constants (margin = 0.5)
#define COS_M   0.8775825618903728f
#define SIN_M   0.479425538604203f
#define MM_C    0.23971276930210156f
#define THRESH  (-0.8775825618903728f)
#define S_SCALE 64.0f

// ---------------------------------------------------------------------------
// Static device scratch (allocations are forbidden)
// ---------------------------------------------------------------------------
__device__ float  g_row_loss[BB];
__device__ float  g_partial[(size_t)BB * NT];
__device__ __half g_kT_h16[(size_t)CC * EE];   // knormT [C][K] fp16 hi
__device__ __half g_kT_l16[(size_t)CC * EE];   // knormT [C][K] fp16 lo
__device__ __half g_emb_h16[(size_t)BB * EE];  // emb [B][K] fp16 (hi only)

// ---------------------------------------------------------------------------
// PTX helpers: baseline (non-'a') instructions only
// ---------------------------------------------------------------------------
__device__ __forceinline__ uint32_t smem_u32(const void* p) {
    uint32_t a;
    asm("{ .reg .u64 t; cvta.to.shared.u64 t, %1; cvt.u32.u64 %0, t; }"
        : "=r"(a) : "l"(p));
    return a;
}

__device__ __forceinline__ void ldsm_x4(uint32_t* r, uint32_t a) {
    asm volatile("ldmatrix.sync.aligned.m8n8.x4.shared.b16 {%0,%1,%2,%3}, [%4];"
        : "=r"(r[0]), "=r"(r[1]), "=r"(r[2]), "=r"(r[3]) : "r"(a));
}
__device__ __forceinline__ void mma_f16(float* d, const uint32_t* a, const uint32_t* b) {
    asm volatile(
        "mma.sync.aligned.m16n8k16.row.col.f32.f16.f16.f32 "
        "{%0,%1,%2,%3}, {%4,%5,%6,%7}, {%8,%9}, {%0,%1,%2,%3};"
        : "+f"(d[0]), "+f"(d[1]), "+f"(d[2]), "+f"(d[3])
        : "r"(a[0]), "r"(a[1]), "r"(a[2]), "r"(a[3]), "r"(b[0]), "r"(b[1]));
}
__device__ __forceinline__ void cp16(uint32_t dst, const void* src, int sz) {
    asm volatile("cp.async.cg.shared.global [%0], [%1], 16, %2;"
        :: "r"(dst), "l"(src), "r"(sz) : "memory");
}
#define CP_COMMIT() asm volatile("cp.async.commit_group;" ::: "memory")
#define CP_WAIT0()  asm volatile("cp.async.wait_group 0;" ::: "memory")
#define CP_WAIT1()  asm volatile("cp.async.wait_group 1;" ::: "memory")

// ---------------------------------------------------------------------------
// Kernel 1 (fused): single pass over ker -> norms + normalized transpose,
// fp16 hi/lo split.
// ---------------------------------------------------------------------------
__global__ __launch_bounds__(256) void prep_ker_fused(const float* __restrict__ ker) {
    __shared__ float sm[32][513];
    __shared__ float s_inv[32];

    const int tid  = threadIdx.x;
    const int lane = tid & 31;
    const int wid  = tid >> 5;
    const int c0   = blockIdx.x * 32;

    #pragma unroll
    for (int i = 0; i < 64; i++) {
        int k = wid + i * 8;
        sm[lane][k] = ker[(size_t)k * CC + (c0 + lane)];
    }
    __syncthreads();

    #pragma unroll
    for (int i = 0; i < 4; i++) {
        int c = wid + i * 8;
        float s = 0.f;
        #pragma unroll
        for (int j = 0; j < 16; j++) {
            float v = sm[c][lane + j * 32];
            s = fmaf(v, v, s);
        }
        #pragma unroll
        for (int off = 16; off > 0; off >>= 1)
            s += __shfl_xor_sync(0xffffffff, s, off);
        if (lane == 0) s_inv[c] = 1.0f / (sqrtf(s) + 1e-6f);
    }
    __syncthreads();

    #pragma unroll
    for (int i = 0; i < 4; i++) {
        int c = wid + i * 8;
        const float inv = s_inv[c];
        size_t base = (size_t)(c0 + c) * EE;
        #pragma unroll
        for (int j = 0; j < 16; j++) {
            int k = lane + j * 32;
            float v = sm[c][k] * inv;
            __half h = __float2half(v);
            g_kT_h16[base + k] = h;
            g_kT_l16[base + k] = __float2half(v - __half2float(h));
        }
    }
}

// ---------------------------------------------------------------------------
// Kernel 2: emb -> fp16 (hi only)
// ---------------------------------------------------------------------------
__global__ void prep_emb_kernel(const float* __restrict__ emb) {
    int i = blockIdx.x * blockDim.x + threadIdx.x;
    if (i >= BB * EE) return;
    g_emb_h16[i] = __float2half(emb[i]);
}

// ---------------------------------------------------------------------------
// Kernel 3: mma.sync fp16 2-term GEMM + fused arcface epilogue.
// 256 threads, 2 CTAs/SM, warp grid 2x4, warp tile 64x32.
// 3-STAGE cp.async pipeline: compute(kc) overlaps load(kc+1) in flight.
// ---------------------------------------------------------------------------
constexpr int ROWB    = 80;                   // 64B data + 16B pad (conflict-free)
constexpr int MATB    = 128 * ROWB;           // 10240 B per matrix
constexpr int STAGEB  = 3 * MATB;             // 30720 B per stage (Ah, Bh, Bl)
constexpr int NSTAGE  = 3;
constexpr int DYNB    = NSTAGE * STAGEB;      // 92160 B dynamic smem

__global__ __launch_bounds__(256, 2) void gemm_mma_kernel(
    const int* __restrict__ label,
    float* __restrict__ out_logits, float* __restrict__ out_cos)
{
    extern __shared__ char dyn[];
    const int tid  = threadIdx.x;
    const int lane = tid & 31;
    const int wid  = tid >> 5;
    const int wm   = wid >> 2;     // 0..1
    const int wn   = wid & 3;      // 0..3
    const int r0 = blockIdx.x * 128;
    const int c0 = blockIdx.y * 128;
    const uint32_t sbase = smem_u32(dyn);

    float acc[4][4][4];
    #pragma unroll
    for (int mt = 0; mt < 4; mt++)
        #pragma unroll
        for (int nt = 0; nt < 4; nt++)
            #pragma unroll
            for (int v = 0; v < 4; v++) acc[mt][nt][v] = 0.f;

    // ---- G->S: 1536 16B-chunks per stage (3 mats x 128 rows x 4), 6/thread ----
    auto load_stage = [&](int s, int kc) {
        const uint32_t stg = sbase + s * STAGEB;
        #pragma unroll
        for (int i = 0; i < 6; i++) {
            int f   = tid + i * 256;
            int m   = f >> 9;          // 0:Ah 1:Bh 2:Bl
            int c   = f & 511;
            int row = c >> 2;
            int ch4 = c & 3;
            uint32_t dst = stg + (uint32_t)(m * MATB + row * ROWB + ch4 * 16);
            const __half* src;
            int sz = 16;
            if (m == 0) {
                src = g_emb_h16 + (size_t)(r0 + row) * EE + kc * 32 + ch4 * 8;
            } else {
                const __half* base = (m == 1) ? g_kT_h16 : g_kT_l16;
                src = base + (size_t)(c0 + row) * EE + kc * 32 + ch4 * 8;
                if (c0 + row >= CC) sz = 0;
            }
            cp16(dst, src, sz);
        }
    };

    // Term-major issue order: same-acc MMAs are 8 issues apart.
    auto compute_stage = [&](int s) {
        const uint32_t st = sbase + s * STAGEB;
        #pragma unroll
        for (int kk = 0; kk < 2; kk++) {
            uint32_t ah[4][4];
            #pragma unroll
            for (int mt = 0; mt < 4; mt++) {
                uint32_t ad = st + (uint32_t)((wm * 64 + mt * 16 + (lane & 15)) * ROWB
                                              + (lane >> 4) * 16 + kk * 32);
                ldsm_x4(ah[mt], ad);
            }
            #pragma unroll
            for (int np = 0; np < 2; np++) {
                uint32_t bh[4], bl[4];
                uint32_t bd = st + MATB
                            + (uint32_t)((wn * 32 + (np * 2 + ((lane >> 4) & 1)) * 8
                                          + (lane & 7)) * ROWB
                                         + ((lane >> 3) & 1) * 16 + kk * 32);
                ldsm_x4(bh, bd);
                ldsm_x4(bl, bd + MATB);
                const int n0 = np * 2, n1 = np * 2 + 1;
                // term 1: Ah*Bh
                #pragma unroll
                for (int mt = 0; mt < 4; mt++) mma_f16(acc[mt][n0], ah[mt], bh + 0);
                #pragma unroll
                for (int mt = 0; mt < 4; mt++) mma_f16(acc[mt][n1], ah[mt], bh + 2);
                // term 2: Ah*Bl
                #pragma unroll
                for (int mt = 0; mt < 4; mt++) mma_f16(acc[mt][n0], ah[mt], bl + 0);
                #pragma unroll
                for (int mt = 0; mt < 4; mt++) mma_f16(acc[mt][n1], ah[mt], bl + 2);
            }
        }
    };

    // ---- 3-stage pipeline over 16 K-chunks of 32 ----
    load_stage(0, 0); CP_COMMIT();
    load_stage(1, 1); CP_COMMIT();
    int sc = 0;   // stage index of kc (kc % 3)
    for (int kc = 0; kc < 16; kc++) {
        if (kc < 15) CP_WAIT1();   // stage kc complete; kc+1 may stay in flight
        else         CP_WAIT0();   // last stage: drain everything
        __syncthreads();
        if (kc + 2 < 16) {
            int sn = sc + 2; if (sn >= 3) sn -= 3;
            load_stage(sn, kc + 2);
            CP_COMMIT();
        }
        compute_stage(sc);
        if (++sc == 3) sc = 0;
    }

    // ---- epilogue: arcface + SCALAR stores + per-row partial sum-exp ----
    const int lq = lane >> 2;
    const int lc = 2 * (lane & 3);
    int lbs[4][2];
    #pragma unroll
    for (int mt = 0; mt < 4; mt++) {
        lbs[mt][0] = label[r0 + wm * 64 + mt * 16 + lq];
        lbs[mt][1] = label[r0 + wm * 64 + mt * 16 + lq + 8];
    }

    float rsum[4][2];
    #pragma unroll
    for (int mt = 0; mt < 4; mt++) { rsum[mt][0] = 0.f; rsum[mt][1] = 0.f; }

    const bool full_tile = (c0 + 128 <= CC);   // true for 781/782 strips

    #pragma unroll
    for (int mt = 0; mt < 4; mt++) {
        #pragma unroll
        for (int nt = 0; nt < 4; nt++) {
            #pragma unroll
            for (int v = 0; v < 4; v++) {
                const int h    = v >> 1;
                const int grow = r0 + wm * 64 + mt * 16 + lq + h * 8;
                const int col  = c0 + wn * 32 + nt * 8 + lc + (v & 1);
                if (full_tile || col < CC) {
                    float cs = acc[mt][nt][v];
                    cs = fminf(1.0f, fmaxf(-1.0f, cs));
                    float o = cs;
                    if (col == lbs[mt][h]) {
                        float sn = sqrtf(fmaxf(0.f, 1.0f - cs * cs));
                        float cm = fmaf(cs, COS_M, -sn * SIN_M);
                        o = (cs - THRESH <= 0.f) ? (cs - MM_C) : cm;
                    }
                    float lg = o * S_SCALE;
                    size_t ga = (size_t)grow * CC + col;
                    out_logits[ga] = lg;
                    out_cos[ga]    = cs;
                    rsum[mt][h] += __expf(lg - 64.0f);
                }
            }
        }
    }

    #pragma unroll
    for (int mt = 0; mt < 4; mt++)
        #pragma unroll
        for (int h = 0; h < 2; h++) {
            float s = rsum[mt][h];
            s += __shfl_xor_sync(0xffffffff, s, 1);
            s += __shfl_xor_sync(0xffffffff, s, 2);
            rsum[mt][h] = s;
        }

    float* srows = (float*)dyn;   // safe: all loads drained + synced below
    __syncthreads();
    if ((lane & 3) == 0) {
        #pragma unroll
        for (int mt = 0; mt < 4; mt++)
            #pragma unroll
            for (int h = 0; h < 2; h++)
                srows[(wm * 64 + mt * 16 + lq + h * 8) * 4 + wn] = rsum[mt][h];
    }
    __syncthreads();
    if (tid < 128) {
        float s = srows[tid * 4 + 0] + srows[tid * 4 + 1]
                + srows[tid * 4 + 2] + srows[tid * 4 + 3];
        g_partial[(size_t)(r0 + tid) * NT + blockIdx.y] = s;
    }
}

// ---------------------------------------------------------------------------
// Kernel 4: per-row reduce of partial sum-exps -> row loss
// ---------------------------------------------------------------------------
__global__ void row_reduce_kernel(const float* __restrict__ out_logits,
                                  const int* __restrict__ label) {
    const int row = blockIdx.x;
    float s = 0.f;
    for (int i = threadIdx.x; i < NT; i += 256)
        s += g_partial[(size_t)row * NT + i];
    __shared__ float sm[256];
    sm[threadIdx.x] = s;
    __syncthreads();
    #pragma unroll
    for (int off = 128; off > 0; off >>= 1) {
        if (threadIdx.x < off) sm[threadIdx.x] += sm[threadIdx.x + off];
        __syncthreads();
    }
    if (threadIdx.x == 0) {
        float logZ = 64.0f + logf(sm[0]);
        g_row_loss[row] = logZ - out_logits[(size_t)row * CC + label[row]];
    }
}

// ---------------------------------------------------------------------------
// Kernel 5: mean over rows -> loss scalar
// ---------------------------------------------------------------------------
__global__ void final_loss_kernel(float* __restrict__ loss_out) {
    __shared__ float sm[BB];
    const int t = threadIdx.x;
    sm[t] = g_row_loss[t];
    __syncthreads();
    #pragma unroll
    for (int off = BB / 2; off > 0; off >>= 1) {
        if (t < off) sm[t] += sm[t + off];
        __syncthreads();
    }
    if (t == 0) loss_out[0] = sm[0] / (float)BB;
}

// ---------------------------------------------------------------------------
extern "C" void kernel_launch(void* const* d_in, const int* in_sizes, int n_in,
                              void* d_out, int out_size) {
    const float* emb   = (const float*)d_in[0];
    const float* ker   = (const float*)d_in[1];
    const int*   label = (const int*)d_in[2];

    float* o          = (float*)d_out;
    float* loss_ptr   = o;
    float* out_logits = o + 1;
    float* out_cos    = o + 1 + (size_t)BB * CC;

    cudaFuncSetAttribute(gemm_mma_kernel,
                         cudaFuncAttributeMaxDynamicSharedMemorySize, DYNB);

    prep_ker_fused<<<CC / 32, 256>>>(ker);
    prep_emb_kernel<<<(BB * EE + 255) / 256, 256>>>(emb);

    dim3 grid(4, NT);   // x fastest: adjacent bids share the ker N-strip in L2
    gemm_mma_kernel<<<grid, 256, DYNB>>>(label, out_logits, out_cos);

    row_reduce_kernel<<<BB, 256>>>(out_logits, label);
    final_loss_kernel<<<1, BB>>>(loss_ptr);
}

// round 12
// speedup vs baseline: 1.5445x; 1.1803x over previous
#include <cuda_runtime.h>
#include <cuda_fp16.h>
#include <math.h>
#include <stdint.h>

// Problem constants
constexpr int BB = 512;      // batch (M)
constexpr int EE = 512;      // embedding dim (K)
constexpr int CC = 100000;   // classes (N)
constexpr int NT = (CC + 127) / 128;   // 782 N-tiles

// ArcFace constants (margin = 0.5)
#define COS_M   0.8775825618903728f
#define SIN_M   0.479425538604203f
#define MM_C    0.23971276930210156f
#define THRESH  (-0.8775825618903728f)
#define S_SCALE 64.0f

// ---------------------------------------------------------------------------
// Static device scratch (allocations are forbidden)
// ---------------------------------------------------------------------------
__device__ float  g_row_loss[BB];
__device__ float  g_partial[(size_t)BB * NT];
__device__ __half g_kT_h16[(size_t)CC * EE];   // knormT [C][K] fp16
__device__ __half g_emb_h16[(size_t)BB * EE];  // emb [B][K] fp16

// ---------------------------------------------------------------------------
// PTX helpers: baseline (non-'a') instructions only
// ---------------------------------------------------------------------------
__device__ __forceinline__ uint32_t smem_u32(const void* p) {
    uint32_t a;
    asm("{ .reg .u64 t; cvta.to.shared.u64 t, %1; cvt.u32.u64 %0, t; }"
        : "=r"(a) : "l"(p));
    return a;
}

__device__ __forceinline__ void ldsm_x4(uint32_t* r, uint32_t a) {
    asm volatile("ldmatrix.sync.aligned.m8n8.x4.shared.b16 {%0,%1,%2,%3}, [%4];"
        : "=r"(r[0]), "=r"(r[1]), "=r"(r[2]), "=r"(r[3]) : "r"(a));
}
__device__ __forceinline__ void mma_f16(float* d, const uint32_t* a, const uint32_t* b) {
    asm volatile(
        "mma.sync.aligned.m16n8k16.row.col.f32.f16.f16.f32 "
        "{%0,%1,%2,%3}, {%4,%5,%6,%7}, {%8,%9}, {%0,%1,%2,%3};"
        : "+f"(d[0]), "+f"(d[1]), "+f"(d[2]), "+f"(d[3])
        : "r"(a[0]), "r"(a[1]), "r"(a[2]), "r"(a[3]), "r"(b[0]), "r"(b[1]));
}
__device__ __forceinline__ void cp16(uint32_t dst, const void* src, int sz) {
    asm volatile("cp.async.cg.shared.global [%0], [%1], 16, %2;"
        :: "r"(dst), "l"(src), "r"(sz) : "memory");
}
#define CP_COMMIT() asm volatile("cp.async.commit_group;" ::: "memory")
#define CP_WAITN(n) asm volatile("cp.async.wait_group %0;" :: "n"(n) : "memory")

// ---------------------------------------------------------------------------
// Kernel 1 (fused): single pass over ker -> norms + normalized transpose fp16
// ---------------------------------------------------------------------------
__global__ __launch_bounds__(256) void prep_ker_fused(const float* __restrict__ ker) {
    __shared__ float sm[32][513];
    __shared__ float s_inv[32];

    const int tid  = threadIdx.x;
    const int lane = tid & 31;
    const int wid  = tid >> 5;
    const int c0   = blockIdx.x * 32;

    #pragma unroll
    for (int i = 0; i < 64; i++) {
        int k = wid + i * 8;
        sm[lane][k] = ker[(size_t)k * CC + (c0 + lane)];
    }
    __syncthreads();

    #pragma unroll
    for (int i = 0; i < 4; i++) {
        int c = wid + i * 8;
        float s = 0.f;
        #pragma unroll
        for (int j = 0; j < 16; j++) {
            float v = sm[c][lane + j * 32];
            s = fmaf(v, v, s);
        }
        #pragma unroll
        for (int off = 16; off > 0; off >>= 1)
            s += __shfl_xor_sync(0xffffffff, s, off);
        if (lane == 0) s_inv[c] = 1.0f / (sqrtf(s) + 1e-6f);
    }
    __syncthreads();

    #pragma unroll
    for (int i = 0; i < 4; i++) {
        int c = wid + i * 8;
        const float inv = s_inv[c];
        size_t base = (size_t)(c0 + c) * EE;
        #pragma unroll
        for (int j = 0; j < 16; j++) {
            int k = lane + j * 32;
            g_kT_h16[base + k] = __float2half(sm[c][k] * inv);
        }
    }
}

// ---------------------------------------------------------------------------
// Kernel 2: emb -> fp16
// ---------------------------------------------------------------------------
__global__ void prep_emb_kernel(const float* __restrict__ emb) {
    int i = blockIdx.x * blockDim.x + threadIdx.x;
    if (i >= BB * EE) return;
    g_emb_h16[i] = __float2half(emb[i]);
}

// ---------------------------------------------------------------------------
// Kernel 3: mma.sync fp16 single-term GEMM + fused arcface epilogue.
// 256 threads, 2 CTAs/SM, warp grid 2x4, warp tile 64x32.
// 4-STAGE cp.async pipeline: two loads in flight behind the computing stage.
// ---------------------------------------------------------------------------
constexpr int ROWB    = 80;                   // 64B data + 16B pad (conflict-free)
constexpr int MATB    = 128 * ROWB;           // 10240 B per matrix
constexpr int STAGEB  = 2 * MATB;             // 20480 B per stage (A, B)
constexpr int NSTAGE  = 4;
constexpr int DYNB    = NSTAGE * STAGEB;      // 81920 B dynamic smem

__global__ __launch_bounds__(256, 2) void gemm_mma_kernel(
    const int* __restrict__ label,
    float* __restrict__ out_logits, float* __restrict__ out_cos)
{
    extern __shared__ char dyn[];
    const int tid  = threadIdx.x;
    const int lane = tid & 31;
    const int wid  = tid >> 5;
    const int wm   = wid >> 2;     // 0..1
    const int wn   = wid & 3;      // 0..3
    const int r0 = blockIdx.x * 128;
    const int c0 = blockIdx.y * 128;
    const uint32_t sbase = smem_u32(dyn);

    float acc[4][4][4];
    #pragma unroll
    for (int mt = 0; mt < 4; mt++)
        #pragma unroll
        for (int nt = 0; nt < 4; nt++)
            #pragma unroll
            for (int v = 0; v < 4; v++) acc[mt][nt][v] = 0.f;

    // ---- G->S: 1024 16B-chunks per stage (2 mats x 128 rows x 4), 4/thread ----
    auto load_stage = [&](int s, int kc) {
        const uint32_t stg = sbase + s * STAGEB;
        #pragma unroll
        for (int i = 0; i < 4; i++) {
            int f   = tid + i * 256;
            int m   = f >> 9;          // 0:A 1:B
            int c   = f & 511;
            int row = c >> 2;
            int ch4 = c & 3;
            uint32_t dst = stg + (uint32_t)(m * MATB + row * ROWB + ch4 * 16);
            const __half* src;
            int sz = 16;
            if (m == 0) {
                src = g_emb_h16 + (size_t)(r0 + row) * EE + kc * 32 + ch4 * 8;
            } else {
                src = g_kT_h16 + (size_t)(c0 + row) * EE + kc * 32 + ch4 * 8;
                if (c0 + row >= CC) sz = 0;
            }
            cp16(dst, src, sz);
        }
    };

    auto compute_stage = [&](int s) {
        const uint32_t st = sbase + s * STAGEB;
        #pragma unroll
        for (int kk = 0; kk < 2; kk++) {
            uint32_t ah[4][4];
            #pragma unroll
            for (int mt = 0; mt < 4; mt++) {
                uint32_t ad = st + (uint32_t)((wm * 64 + mt * 16 + (lane & 15)) * ROWB
                                              + (lane >> 4) * 16 + kk * 32);
                ldsm_x4(ah[mt], ad);
            }
            #pragma unroll
            for (int np = 0; np < 2; np++) {
                uint32_t bh[4];
                uint32_t bd = st + MATB
                            + (uint32_t)((wn * 32 + (np * 2 + ((lane >> 4) & 1)) * 8
                                          + (lane & 7)) * ROWB
                                         + ((lane >> 3) & 1) * 16 + kk * 32);
                ldsm_x4(bh, bd);
                const int n0 = np * 2, n1 = np * 2 + 1;
                #pragma unroll
                for (int mt = 0; mt < 4; mt++) mma_f16(acc[mt][n0], ah[mt], bh + 0);
                #pragma unroll
                for (int mt = 0; mt < 4; mt++) mma_f16(acc[mt][n1], ah[mt], bh + 2);
            }
        }
    };

    // ---- 4-stage pipeline over 16 K-chunks of 32 ----
    load_stage(0, 0); CP_COMMIT();
    load_stage(1, 1); CP_COMMIT();
    load_stage(2, 2); CP_COMMIT();
    int sc = 0;   // stage of kc (kc % 4)
    for (int kc = 0; kc < 16; kc++) {
        // ensure stage kc is complete; up to 2 younger groups may stay in flight
        if      (kc < 14) CP_WAITN(2);
        else if (kc == 14) CP_WAITN(1);
        else               CP_WAITN(0);
        __syncthreads();
        if (kc + 3 < 16) {
            int sn = sc + 3; if (sn >= NSTAGE) sn -= NSTAGE;
            load_stage(sn, kc + 3);
            CP_COMMIT();
        }
        compute_stage(sc);
        if (++sc == NSTAGE) sc = 0;
    }

    // ---- epilogue: arcface + SCALAR stores + per-row partial sum-exp ----
    const int lq = lane >> 2;
    const int lc = 2 * (lane & 3);
    int lbs[4][2];
    #pragma unroll
    for (int mt = 0; mt < 4; mt++) {
        lbs[mt][0] = label[r0 + wm * 64 + mt * 16 + lq];
        lbs[mt][1] = label[r0 + wm * 64 + mt * 16 + lq + 8];
    }

    float rsum[4][2];
    #pragma unroll
    for (int mt = 0; mt < 4; mt++) { rsum[mt][0] = 0.f; rsum[mt][1] = 0.f; }

    const bool full_tile = (c0 + 128 <= CC);   // true for 781/782 strips

    #pragma unroll
    for (int mt = 0; mt < 4; mt++) {
        #pragma unroll
        for (int nt = 0; nt < 4; nt++) {
            #pragma unroll
            for (int v = 0; v < 4; v++) {
                const int h    = v >> 1;
                const int grow = r0 + wm * 64 + mt * 16 + lq + h * 8;
                const int col  = c0 + wn * 32 + nt * 8 + lc + (v & 1);
                if (full_tile || col < CC) {
                    float cs = acc[mt][nt][v];
                    cs = fminf(1.0f, fmaxf(-1.0f, cs));
                    float o = cs;
                    if (col == lbs[mt][h]) {
                        float sn = sqrtf(fmaxf(0.f, 1.0f - cs * cs));
                        float cm = fmaf(cs, COS_M, -sn * SIN_M);
                        o = (cs - THRESH <= 0.f) ? (cs - MM_C) : cm;
                    }
                    float lg = o * S_SCALE;
                    size_t ga = (size_t)grow * CC + col;
                    out_logits[ga] = lg;
                    out_cos[ga]    = cs;
                    rsum[mt][h] += __expf(lg - 64.0f);
                }
            }
        }
    }

    #pragma unroll
    for (int mt = 0; mt < 4; mt++)
        #pragma unroll
        for (int h = 0; h < 2; h++) {
            float s = rsum[mt][h];
            s += __shfl_xor_sync(0xffffffff, s, 1);
            s += __shfl_xor_sync(0xffffffff, s, 2);
            rsum[mt][h] = s;
        }

    float* srows = (float*)dyn;   // safe: all loads drained
    __syncthreads();
    if ((lane & 3) == 0) {
        #pragma unroll
        for (int mt = 0; mt < 4; mt++)
            #pragma unroll
            for (int h = 0; h < 2; h++)
                srows[(wm * 64 + mt * 16 + lq + h * 8) * 4 + wn] = rsum[mt][h];
    }
    __syncthreads();
    if (tid < 128) {
        float s = srows[tid * 4 + 0] + srows[tid * 4 + 1]
                + srows[tid * 4 + 2] + srows[tid * 4 + 3];
        g_partial[(size_t)(r0 + tid) * NT + blockIdx.y] = s;
    }
}

// ---------------------------------------------------------------------------
// Kernel 4: per-row reduce of partial sum-exps -> row loss
// ---------------------------------------------------------------------------
__global__ void row_reduce_kernel(const float* __restrict__ out_logits,
                                  const int* __restrict__ label) {
    const int row = blockIdx.x;
    float s = 0.f;
    for (int i = threadIdx.x; i < NT; i += 256)
        s += g_partial[(size_t)row * NT + i];
    __shared__ float sm[256];
    sm[threadIdx.x] = s;
    __syncthreads();
    #pragma unroll
    for (int off = 128; off > 0; off >>= 1) {
        if (threadIdx.x < off) sm[threadIdx.x] += sm[threadIdx.x + off];
        __syncthreads();
    }
    if (threadIdx.x == 0) {
        float logZ = 64.0f + logf(sm[0]);
        g_row_loss[row] = logZ - out_logits[(size_t)row * CC + label[row]];
    }
}

// ---------------------------------------------------------------------------
// Kernel 5: mean over rows -> loss scalar
// ---------------------------------------------------------------------------
__global__ void final_loss_kernel(float* __restrict__ loss_out) {
    __shared__ float sm[BB];
    const int t = threadIdx.x;
    sm[t] = g_row_loss[t];
    __syncthreads();
    #pragma unroll
    for (int off = BB / 2; off > 0; off >>= 1) {
        if (t < off) sm[t] += sm[t + off];
        __syncthreads();
    }
    if (t == 0) loss_out[0] = sm[0] / (float)BB;
}

// ---------------------------------------------------------------------------
extern "C" void kernel_launch(void* const* d_in, const int* in_sizes, int n_in,
                              void* d_out, int out_size) {
    const float* emb   = (const float*)d_in[0];
    const float* ker   = (const float*)d_in[1];
    const int*   label = (const int*)d_in[2];

    float* o          = (float*)d_out;
    float* loss_ptr   = o;
    float* out_logits = o + 1;
    float* out_cos    = o + 1 + (size_t)BB * CC;

    cudaFuncSetAttribute(gemm_mma_kernel,
                         cudaFuncAttributeMaxDynamicSharedMemorySize, DYNB);

    prep_ker_fused<<<CC / 32, 256>>>(ker);
    prep_emb_kernel<<<(BB * EE + 255) / 256, 256>>>(emb);

    dim3 grid(4, NT);   // x fastest: adjacent bids share the ker N-strip in L2
    gemm_mma_kernel<<<grid, 256, DYNB>>>(label, out_logits, out_cos);

    row_reduce_kernel<<<BB, 256>>>(out_logits, label);
    final_loss_kernel<<<1, BB>>>(loss_ptr);
}

// round 13
// speedup vs baseline: 1.5669x; 1.0145x over previous
#include <cuda_runtime.h>
#include <cuda_fp16.h>
#include <math.h>
#include <stdint.h>

// Problem constants
constexpr int BB = 512;      // batch (M)
constexpr int EE = 512;      // embedding dim (K)
constexpr int CC = 100000;   // classes (N)
constexpr int NT = (CC + 127) / 128;   // 782 N-tiles

// ArcFace constants (margin = 0.5)
#define COS_M   0.8775825618903728f
#define SIN_M   0.479425538604203f
#define MM_C    0.23971276930210156f
#define THRESH  (-0.8775825618903728f)
#define S_SCALE 64.0f

// ---------------------------------------------------------------------------
// Static device scratch (allocations are forbidden)
// ---------------------------------------------------------------------------
__device__ float  g_row_loss[BB];
__device__ float  g_partial[(size_t)BB * NT];
__device__ __half g_kT_h16[(size_t)CC * EE];   // knormT [C][K] fp16
__device__ __half g_emb_h16[(size_t)BB * EE];  // emb [B][K] fp16

// ---------------------------------------------------------------------------
// PTX helpers: baseline (non-'a') instructions only
// ---------------------------------------------------------------------------
__device__ __forceinline__ uint32_t smem_u32(const void* p) {
    uint32_t a;
    asm("{ .reg .u64 t; cvta.to.shared.u64 t, %1; cvt.u32.u64 %0, t; }"
        : "=r"(a) : "l"(p));
    return a;
}

__device__ __forceinline__ void ldsm_x4(uint32_t* r, uint32_t a) {
    asm volatile("ldmatrix.sync.aligned.m8n8.x4.shared.b16 {%0,%1,%2,%3}, [%4];"
        : "=r"(r[0]), "=r"(r[1]), "=r"(r[2]), "=r"(r[3]) : "r"(a));
}
__device__ __forceinline__ void mma_f16(float* d, const uint32_t* a, const uint32_t* b) {
    asm volatile(
        "mma.sync.aligned.m16n8k16.row.col.f32.f16.f16.f32 "
        "{%0,%1,%2,%3}, {%4,%5,%6,%7}, {%8,%9}, {%0,%1,%2,%3};"
        : "+f"(d[0]), "+f"(d[1]), "+f"(d[2]), "+f"(d[3])
        : "r"(a[0]), "r"(a[1]), "r"(a[2]), "r"(a[3]), "r"(b[0]), "r"(b[1]));
}
__device__ __forceinline__ void cp16(uint32_t dst, const void* src, int sz) {
    asm volatile("cp.async.cg.shared.global [%0], [%1], 16, %2;"
        :: "r"(dst), "l"(src), "r"(sz) : "memory");
}
__device__ __forceinline__ float ex2_approx(float x) {
    float r;
    asm("ex2.approx.f32 %0, %1;" : "=f"(r) : "f"(x));
    return r;
}
#define CP_COMMIT() asm volatile("cp.async.commit_group;" ::: "memory")
#define CP_WAIT0()  asm volatile("cp.async.wait_group 0;" ::: "memory")

// log2(e) * 64 : exp(64*(o-1)) = 2^(92.332482*(o-1))
#define EXP_C 92.33248262f

// ---------------------------------------------------------------------------
// Kernel 1 (fused): single pass over ker -> norms + normalized transpose fp16
// ---------------------------------------------------------------------------
__global__ __launch_bounds__(256) void prep_ker_fused(const float* __restrict__ ker) {
    __shared__ float sm[32][513];
    __shared__ float s_inv[32];

    const int tid  = threadIdx.x;
    const int lane = tid & 31;
    const int wid  = tid >> 5;
    const int c0   = blockIdx.x * 32;

    #pragma unroll
    for (int i = 0; i < 64; i++) {
        int k = wid + i * 8;
        sm[lane][k] = ker[(size_t)k * CC + (c0 + lane)];
    }
    __syncthreads();

    #pragma unroll
    for (int i = 0; i < 4; i++) {
        int c = wid + i * 8;
        float s = 0.f;
        #pragma unroll
        for (int j = 0; j < 16; j++) {
            float v = sm[c][lane + j * 32];
            s = fmaf(v, v, s);
        }
        #pragma unroll
        for (int off = 16; off > 0; off >>= 1)
            s += __shfl_xor_sync(0xffffffff, s, off);
        if (lane == 0) s_inv[c] = 1.0f / (sqrtf(s) + 1e-6f);
    }
    __syncthreads();

    #pragma unroll
    for (int i = 0; i < 4; i++) {
        int c = wid + i * 8;
        const float inv = s_inv[c];
        size_t base = (size_t)(c0 + c) * EE;
        #pragma unroll
        for (int j = 0; j < 16; j++) {
            int k = lane + j * 32;
            g_kT_h16[base + k] = __float2half(sm[c][k] * inv);
        }
    }
}

// ---------------------------------------------------------------------------
// Kernel 2: emb -> fp16
// ---------------------------------------------------------------------------
__global__ void prep_emb_kernel(const float* __restrict__ emb) {
    int i = blockIdx.x * blockDim.x + threadIdx.x;
    if (i >= BB * EE) return;
    g_emb_h16[i] = __float2half(emb[i]);
}

// ---------------------------------------------------------------------------
// Kernel 3: mma.sync fp16 single-term GEMM + fused arcface epilogue.
// 256 threads, 2 CTAs/SM, warp grid 2x4, warp tile 64x32.
// KCH=64: 8 kc epochs (half the barriers), 2-stage double buffer.
// ---------------------------------------------------------------------------
constexpr int ROWB    = 144;                  // 128B data + 16B pad (conflict-free)
constexpr int MATB    = 128 * ROWB;           // 18432 B per matrix
constexpr int STAGEB  = 2 * MATB;             // 36864 B per stage (A, B)
constexpr int DYNB    = 2 * STAGEB;           // 73728 B dynamic smem

__global__ __launch_bounds__(256, 2) void gemm_mma_kernel(
    const int* __restrict__ label,
    float* __restrict__ out_logits, float* __restrict__ out_cos)
{
    extern __shared__ char dyn[];
    const int tid  = threadIdx.x;
    const int lane = tid & 31;
    const int wid  = tid >> 5;
    const int wm   = wid >> 2;     // 0..1
    const int wn   = wid & 3;      // 0..3
    const int r0 = blockIdx.x * 128;
    const int c0 = blockIdx.y * 128;
    const uint32_t sbase = smem_u32(dyn);

    float acc[4][4][4];
    #pragma unroll
    for (int mt = 0; mt < 4; mt++)
        #pragma unroll
        for (int nt = 0; nt < 4; nt++)
            #pragma unroll
            for (int v = 0; v < 4; v++) acc[mt][nt][v] = 0.f;

    // ---- G->S: 2048 16B-chunks per stage (2 mats x 128 rows x 8), 8/thread ----
    auto load_stage = [&](int s, int kc) {
        const uint32_t stg = sbase + s * STAGEB;
        #pragma unroll
        for (int i = 0; i < 8; i++) {
            int f   = tid + i * 256;
            int m   = f >> 10;         // 0:A 1:B
            int c   = f & 1023;
            int row = c >> 3;
            int ch  = c & 7;
            uint32_t dst = stg + (uint32_t)(m * MATB + row * ROWB + ch * 16);
            const __half* src;
            int sz = 16;
            if (m == 0) {
                src = g_emb_h16 + (size_t)(r0 + row) * EE + kc * 64 + ch * 8;
            } else {
                src = g_kT_h16 + (size_t)(c0 + row) * EE + kc * 64 + ch * 8;
                if (c0 + row >= CC) sz = 0;
            }
            cp16(dst, src, sz);
        }
    };

    auto compute_stage = [&](int s) {
        const uint32_t st = sbase + s * STAGEB;
        #pragma unroll
        for (int kk = 0; kk < 4; kk++) {
            uint32_t ah[4][4];
            #pragma unroll
            for (int mt = 0; mt < 4; mt++) {
                uint32_t ad = st + (uint32_t)((wm * 64 + mt * 16 + (lane & 15)) * ROWB
                                              + (lane >> 4) * 16 + kk * 32);
                ldsm_x4(ah[mt], ad);
            }
            #pragma unroll
            for (int np = 0; np < 2; np++) {
                uint32_t bh[4];
                uint32_t bd = st + MATB
                            + (uint32_t)((wn * 32 + (np * 2 + ((lane >> 4) & 1)) * 8
                                          + (lane & 7)) * ROWB
                                         + ((lane >> 3) & 1) * 16 + kk * 32);
                ldsm_x4(bh, bd);
                const int n0 = np * 2, n1 = np * 2 + 1;
                #pragma unroll
                for (int mt = 0; mt < 4; mt++) mma_f16(acc[mt][n0], ah[mt], bh + 0);
                #pragma unroll
                for (int mt = 0; mt < 4; mt++) mma_f16(acc[mt][n1], ah[mt], bh + 2);
            }
        }
    };

    // ---- 2-stage pipeline over 8 K-chunks of 64 ----
    load_stage(0, 0);
    CP_COMMIT();
    CP_WAIT0();
    __syncthreads();
    for (int kc = 0; kc < 8; kc++) {
        if (kc < 7) { load_stage((kc + 1) & 1, kc + 1); CP_COMMIT(); }
        compute_stage(kc & 1);
        CP_WAIT0();
        __syncthreads();
    }

    // ---- epilogue: arcface + SCALAR stores + per-row partial sum-exp ----
    const int lq = lane >> 2;
    const int lc = 2 * (lane & 3);
    int lbs[4][2];
    #pragma unroll
    for (int mt = 0; mt < 4; mt++) {
        lbs[mt][0] = label[r0 + wm * 64 + mt * 16 + lq];
        lbs[mt][1] = label[r0 + wm * 64 + mt * 16 + lq + 8];
    }

    float rsum[4][2];
    #pragma unroll
    for (int mt = 0; mt < 4; mt++) { rsum[mt][0] = 0.f; rsum[mt][1] = 0.f; }

    const bool full_tile = (c0 + 128 <= CC);   // true for 781/782 strips

    #pragma unroll
    for (int mt = 0; mt < 4; mt++) {
        #pragma unroll
        for (int nt = 0; nt < 4; nt++) {
            #pragma unroll
            for (int v = 0; v < 4; v++) {
                const int h    = v >> 1;
                const int grow = r0 + wm * 64 + mt * 16 + lq + h * 8;
                const int col  = c0 + wn * 32 + nt * 8 + lc + (v & 1);
                if (full_tile || col < CC) {
                    float cs = acc[mt][nt][v];
                    cs = fminf(1.0f, fmaxf(-1.0f, cs));
                    float o = cs;
                    if (col == lbs[mt][h]) {
                        float sn = sqrtf(fmaxf(0.f, 1.0f - cs * cs));
                        float cm = fmaf(cs, COS_M, -sn * SIN_M);
                        o = (cs - THRESH <= 0.f) ? (cs - MM_C) : cm;
                    }
                    float lg = o * S_SCALE;
                    size_t ga = (size_t)grow * CC + col;
                    out_logits[ga] = lg;
                    out_cos[ga]    = cs;
                    // exp(lg - 64) = 2^(EXP_C * (o - 1))
                    rsum[mt][h] += ex2_approx(fmaf(o, EXP_C, -EXP_C));
                }
            }
        }
    }

    #pragma unroll
    for (int mt = 0; mt < 4; mt++)
        #pragma unroll
        for (int h = 0; h < 2; h++) {
            float s = rsum[mt][h];
            s += __shfl_xor_sync(0xffffffff, s, 1);
            s += __shfl_xor_sync(0xffffffff, s, 2);
            rsum[mt][h] = s;
        }

    float* srows = (float*)dyn;   // safe: all loads drained
    __syncthreads();
    if ((lane & 3) == 0) {
        #pragma unroll
        for (int mt = 0; mt < 4; mt++)
            #pragma unroll
            for (int h = 0; h < 2; h++)
                srows[(wm * 64 + mt * 16 + lq + h * 8) * 4 + wn] = rsum[mt][h];
    }
    __syncthreads();
    if (tid < 128) {
        float s = srows[tid * 4 + 0] + srows[tid * 4 + 1]
                + srows[tid * 4 + 2] + srows[tid * 4 + 3];
        g_partial[(size_t)(r0 + tid) * NT + blockIdx.y] = s;
    }
}

// ---------------------------------------------------------------------------
// Kernel 4: per-row reduce of partial sum-exps -> row loss
// ---------------------------------------------------------------------------
__global__ void row_reduce_kernel(const float* __restrict__ out_logits,
                                  const int* __restrict__ label) {
    const int row = blockIdx.x;
    float s = 0.f;
    for (int i = threadIdx.x; i < NT; i += 256)
        s += g_partial[(size_t)row * NT + i];
    __shared__ float sm[256];
    sm[threadIdx.x] = s;
    __syncthreads();
    #pragma unroll
    for (int off = 128; off > 0; off >>= 1) {
        if (threadIdx.x < off) sm[threadIdx.x] += sm[threadIdx.x + off];
        __syncthreads();
    }
    if (threadIdx.x == 0) {
        float logZ = 64.0f + logf(sm[0]);
        g_row_loss[row] = logZ - out_logits[(size_t)row * CC + label[row]];
    }
}

// ---------------------------------------------------------------------------
// Kernel 5: mean over rows -> loss scalar
// ---------------------------------------------------------------------------
__global__ void final_loss_kernel(float* __restrict__ loss_out) {
    __shared__ float sm[BB];
    const int t = threadIdx.x;
    sm[t] = g_row_loss[t];
    __syncthreads();
    #pragma unroll
    for (int off = BB / 2; off > 0; off >>= 1) {
        if (t < off) sm[t] += sm[t + off];
        __syncthreads();
    }
    if (t == 0) loss_out[0] = sm[0] / (float)BB;
}

// ---------------------------------------------------------------------------
extern "C" void kernel_launch(void* const* d_in, const int* in_sizes, int n_in,
                              void* d_out, int out_size) {
    const float* emb   = (const float*)d_in[0];
    const float* ker   = (const float*)d_in[1];
    const int*   label = (const int*)d_in[2];

    float* o          = (float*)d_out;
    float* loss_ptr   = o;
    float* out_logits = o + 1;
    float* out_cos    = o + 1 + (size_t)BB * CC;

    cudaFuncSetAttribute(gemm_mma_kernel,
                         cudaFuncAttributeMaxDynamicSharedMemorySize, DYNB);

    prep_ker_fused<<<CC / 32, 256>>>(ker);
    prep_emb_kernel<<<(BB * EE + 255) / 256, 256>>>(emb);

    dim3 grid(4, NT);   // x fastest: adjacent bids share the ker N-strip in L2
    gemm_mma_kernel<<<grid, 256, DYNB>>>(label, out_logits, out_cos);

    row_reduce_kernel<<<BB, 256>>>(out_logits, label);
    final_loss_kernel<<<1, BB>>>(loss_ptr);
}